// round 3
// baseline (speedup 1.0000x reference)
#include <cuda_runtime.h>

#define N_VOX   262144
#define M_PAIRS 131072
#define K_OFF   27
#define C       32
#define TOTAL_PAIRS (K_OFF * M_PAIRS)      // 3,538,944
#define NUM_SCAN_BLOCKS (N_VOX / 1024)     // 256

// ---------------- scratch (device globals; no runtime allocation) ----------
__device__ float g_contrib[(size_t)TOTAL_PAIRS * C];   // 453 MB, row-grouped slots
__device__ int   g_pos[TOTAL_PAIRS];                   // pair -> slot index
__device__ int   g_cnt[N_VOX];                         // contributions per out row
__device__ int   g_cur[N_VOX];                         // slot cursor per out row
__device__ int   g_rowstart[N_VOX];                    // exclusive scan of g_cnt
__device__ int   g_blocksum[NUM_SCAN_BLOCKS];

// ---------------------------------------------------------------------------
// K0: zero counters
// ---------------------------------------------------------------------------
__global__ void zero_kernel()
{
    int i = blockIdx.x * blockDim.x + threadIdx.x;
    if (i < N_VOX) { g_cnt[i] = 0; g_cur[i] = 0; }
}

// ---------------------------------------------------------------------------
// K1: histogram of out_map
// ---------------------------------------------------------------------------
__global__ void count_kernel(const int* __restrict__ out_map)
{
    int i = blockIdx.x * blockDim.x + threadIdx.x;
    if (i < TOTAL_PAIRS) atomicAdd(&g_cnt[__ldg(out_map + i)], 1);
}

// ---------------------------------------------------------------------------
// K2a: per-1024-block exclusive scan; emit block sums
// ---------------------------------------------------------------------------
__global__ void scan_block_kernel()
{
    __shared__ int s[1024];
    int t = threadIdx.x;
    int i = blockIdx.x * 1024 + t;
    int v = g_cnt[i];
    s[t] = v;
    __syncthreads();
    // Hillis-Steele inclusive scan
    for (int off = 1; off < 1024; off <<= 1) {
        int add = (t >= off) ? s[t - off] : 0;
        __syncthreads();
        s[t] += add;
        __syncthreads();
    }
    g_rowstart[i] = s[t] - v;                 // exclusive within block
    if (t == 1023) g_blocksum[blockIdx.x] = s[t];
}

// ---------------------------------------------------------------------------
// K2b: exclusive scan of the 256 block sums (single block)
// ---------------------------------------------------------------------------
__global__ void scan_top_kernel()
{
    __shared__ int s[NUM_SCAN_BLOCKS];
    int t = threadIdx.x;
    int v = g_blocksum[t];
    s[t] = v;
    __syncthreads();
    for (int off = 1; off < NUM_SCAN_BLOCKS; off <<= 1) {
        int add = (t >= off) ? s[t - off] : 0;
        __syncthreads();
        s[t] += add;
        __syncthreads();
    }
    g_blocksum[t] = s[t] - v;                 // exclusive
}

// ---------------------------------------------------------------------------
// K2c: add block offsets
// ---------------------------------------------------------------------------
__global__ void scan_add_kernel()
{
    int i = blockIdx.x * blockDim.x + threadIdx.x;
    if (i < N_VOX) g_rowstart[i] += g_blocksum[i >> 10];
}

// ---------------------------------------------------------------------------
// K3: assign each pair its CSR slot
// ---------------------------------------------------------------------------
__global__ void fill_pos_kernel(const int* __restrict__ out_map)
{
    int i = blockIdx.x * blockDim.x + threadIdx.x;
    if (i < TOTAL_PAIRS) {
        int o = __ldg(out_map + i);
        int slot = atomicAdd(&g_cur[o], 1);
        g_pos[i] = g_rowstart[o] + slot;
    }
}

// ---------------------------------------------------------------------------
// K4: k-major gather GEMM; plain scattered STORE into CSR slot (no atomics)
// ---------------------------------------------------------------------------
#define WARPS_PER_BLOCK 8
#define PAIRS_PER_WARP  16

__global__ __launch_bounds__(WARPS_PER_BLOCK * 32)
void gemm_store_kernel(const float* __restrict__ input,
                       const float* __restrict__ kernel,
                       const int*   __restrict__ in_map)
{
    const int k    = blockIdx.y;
    const int lane = threadIdx.x & 31;
    const int warp = threadIdx.x >> 5;

    // Register-resident weight column: w[i] = W[k][i][lane]
    float w[C];
    const float* Wk = kernel + k * C * C;
    #pragma unroll
    for (int i = 0; i < C; i++) w[i] = __ldg(Wk + i * C + lane);

    const int* im  = in_map + k * M_PAIRS;
    const int* pp  = g_pos  + k * M_PAIRS;

    const int base = (blockIdx.x * WARPS_PER_BLOCK + warp) * PAIRS_PER_WARP;

    #pragma unroll 4
    for (int p = 0; p < PAIRS_PER_WARP; p++) {
        const int m    = base + p;
        const int irow = __ldg(im + m);
        const int slot = __ldg(pp + m);

        const float4* row4 = (const float4*)(input + (size_t)irow * C);

        float acc = 0.f;
        #pragma unroll
        for (int j = 0; j < C / 4; j++) {
            float4 a = __ldg(row4 + j);          // uniform across warp -> broadcast
            acc = fmaf(a.x, w[4 * j + 0], acc);
            acc = fmaf(a.y, w[4 * j + 1], acc);
            acc = fmaf(a.z, w[4 * j + 2], acc);
            acc = fmaf(a.w, w[4 * j + 3], acc);
        }

        g_contrib[(size_t)slot * C + lane] = acc;   // coalesced 128B scattered store
    }
}

// ---------------------------------------------------------------------------
// K5: per-row reduction of contiguous CSR slots + bias; one store per row
// ---------------------------------------------------------------------------
__global__ __launch_bounds__(256)
void reduce_kernel(const float* __restrict__ bias,
                   float*       __restrict__ out)
{
    const int lane = threadIdx.x & 31;
    const int row  = (blockIdx.x * blockDim.x + threadIdx.x) >> 5;
    if (row >= N_VOX) return;

    const int base = g_rowstart[row];
    const int n    = g_cnt[row];

    float a0 = __ldg(bias + lane);
    float a1 = 0.f, a2 = 0.f, a3 = 0.f;

    const float* src = g_contrib + (size_t)base * C + lane;
    int e = 0;
    for (; e + 4 <= n; e += 4) {               // 4-way MLP on the add chain
        a0 += __ldg(src + (size_t)(e + 0) * C);
        a1 += __ldg(src + (size_t)(e + 1) * C);
        a2 += __ldg(src + (size_t)(e + 2) * C);
        a3 += __ldg(src + (size_t)(e + 3) * C);
    }
    for (; e < n; e++) a0 += __ldg(src + (size_t)e * C);

    out[(size_t)row * C + lane] = (a0 + a1) + (a2 + a3);
}

// ---------------------------------------------------------------------------
// Launch
// ---------------------------------------------------------------------------
extern "C" void kernel_launch(void* const* d_in, const int* in_sizes, int n_in,
                              void* d_out, int out_size)
{
    const float* input   = (const float*)d_in[0];
    const float* kernelw = (const float*)d_in[1];
    const float* bias    = (const float*)d_in[2];
    const int*   in_map  = (const int*)  d_in[3];
    const int*   out_map = (const int*)  d_in[4];
    float*       out     = (float*)d_out;

    zero_kernel<<<(N_VOX + 255) / 256, 256>>>();
    count_kernel<<<(TOTAL_PAIRS + 255) / 256, 256>>>(out_map);
    scan_block_kernel<<<NUM_SCAN_BLOCKS, 1024>>>();
    scan_top_kernel<<<1, NUM_SCAN_BLOCKS>>>();
    scan_add_kernel<<<(N_VOX + 255) / 256, 256>>>();
    fill_pos_kernel<<<(TOTAL_PAIRS + 255) / 256, 256>>>(out_map);

    dim3 grid(M_PAIRS / (WARPS_PER_BLOCK * PAIRS_PER_WARP), K_OFF);
    gemm_store_kernel<<<grid, WARPS_PER_BLOCK * 32>>>(input, kernelw, in_map);

    reduce_kernel<<<(N_VOX * 32 + 255) / 256, 256>>>(bias, out);
}

// round 4
// speedup vs baseline: 1.2625x; 1.2625x over previous
#include <cuda_runtime.h>
#include <cstdint>

#define N_VOX   262144
#define M_PAIRS 131072
#define K_OFF   27
#define C       32

// ---------------------------------------------------------------------------
// Kernel 1: out[n][c] = bias[c]  (bias add commutes with the scatter-adds)
// ---------------------------------------------------------------------------
__global__ void bias_init_kernel(float* __restrict__ out,
                                 const float* __restrict__ bias)
{
    int t = blockIdx.x * blockDim.x + threadIdx.x;
    const int total4 = N_VOX * (C / 4);
    if (t < total4) {
        const float4* b4 = (const float4*)bias;
        float4* o4 = (float4*)out;
        o4[t] = b4[t & 7];
    }
}

// ---------------------------------------------------------------------------
// Kernel 2: gather -> f32x2-packed GEMM -> TMA bulk-reduction scatter-add.
//   - one warp per 16 pairs, lane = out channel, W[k] column packed into
//     16 b64 registers (f32x2 pairs)
//   - per pair: 8 uniform LDG.128 (warp broadcast), 16 fma.rn.f32x2, 1 STS
//   - scatter: elected lane issues cp.reduce.async.bulk (128B, add.f32) per
//     pair; reduction happens in the TMA/L2 path, NOT the per-lane LSU.
// ---------------------------------------------------------------------------
#define WARPS_PER_BLOCK 8
#define PAIRS_PER_WARP  16

__device__ __forceinline__ uint32_t smem_u32(const void* p) {
    uint32_t a;
    asm("{ .reg .u64 t; cvta.to.shared.u64 t, %1; cvt.u32.u64 %0, t; }"
        : "=r"(a) : "l"(p));
    return a;
}

__global__ __launch_bounds__(WARPS_PER_BLOCK * 32)
void scatter_gemm_kernel(const float* __restrict__ input,
                         const float* __restrict__ kernel,
                         const int*   __restrict__ in_map,
                         const int*   __restrict__ out_map,
                         float*       __restrict__ out)
{
    __shared__ float sbuf[WARPS_PER_BLOCK][PAIRS_PER_WARP][C];   // 16 KB

    const int k    = blockIdx.y;
    const int lane = threadIdx.x & 31;
    const int warp = threadIdx.x >> 5;

    // Weight column for this lane, packed into f32x2 register pairs:
    // wp[j] = (W[k][2j][lane], W[k][2j+1][lane])
    const float* Wk = kernel + k * C * C;
    unsigned long long wp[C / 2];
    #pragma unroll
    for (int j = 0; j < C / 2; j++) {
        float w0 = __ldg(Wk + (2 * j)     * C + lane);
        float w1 = __ldg(Wk + (2 * j + 1) * C + lane);
        asm("mov.b64 %0, {%1, %2};" : "=l"(wp[j]) : "f"(w0), "f"(w1));
    }

    const int* im = in_map  + k * M_PAIRS;
    const int* om = out_map + k * M_PAIRS;

    const int base = (blockIdx.x * WARPS_PER_BLOCK + warp) * PAIRS_PER_WARP;

    #pragma unroll 4
    for (int p = 0; p < PAIRS_PER_WARP; p++) {
        const int irow = __ldg(im + base + p);
        const float4* row4 = (const float4*)(input + (size_t)irow * C);

        unsigned long long acc = 0ULL;      // packed (0.f, 0.f)
        #pragma unroll
        for (int j = 0; j < C / 4; j++) {
            float4 a = __ldg(row4 + j);     // uniform across warp -> broadcast
            unsigned long long a01, a23;
            asm("mov.b64 %0, {%1, %2};" : "=l"(a01) : "f"(a.x), "f"(a.y));
            asm("mov.b64 %0, {%1, %2};" : "=l"(a23) : "f"(a.z), "f"(a.w));
            asm("fma.rn.f32x2 %0, %1, %2, %0;" : "+l"(acc) : "l"(a01), "l"(wp[2 * j]));
            asm("fma.rn.f32x2 %0, %1, %2, %0;" : "+l"(acc) : "l"(a23), "l"(wp[2 * j + 1]));
        }
        float lo, hi;
        asm("mov.b64 {%0, %1}, %2;" : "=f"(lo), "=f"(hi) : "l"(acc));

        sbuf[warp][p][lane] = lo + hi;
    }

    __syncwarp();

    if (lane == 0) {
        // Make the generic-proxy STS data visible to the async (TMA) proxy.
        asm volatile("fence.proxy.async.shared::cta;" ::: "memory");

        #pragma unroll
        for (int p = 0; p < PAIRS_PER_WARP; p++) {
            const int orow = __ldg(om + base + p);
            float* dst = out + (size_t)orow * C;
            uint32_t src = smem_u32(&sbuf[warp][p][0]);
            asm volatile(
                "cp.reduce.async.bulk.global.shared::cta.bulk_group.add.f32 "
                "[%0], [%1], 128;"
                :: "l"(dst), "r"(src) : "memory");
        }
        asm volatile("cp.async.bulk.commit_group;" ::: "memory");
        asm volatile("cp.async.bulk.wait_group 0;" ::: "memory");
    }
}

// ---------------------------------------------------------------------------
// Launch
// ---------------------------------------------------------------------------
extern "C" void kernel_launch(void* const* d_in, const int* in_sizes, int n_in,
                              void* d_out, int out_size)
{
    const float* input   = (const float*)d_in[0];
    const float* kernelw = (const float*)d_in[1];
    const float* bias    = (const float*)d_in[2];
    const int*   in_map  = (const int*)  d_in[3];
    const int*   out_map = (const int*)  d_in[4];
    float*       out     = (float*)d_out;

    const int total4 = N_VOX * (C / 4);
    bias_init_kernel<<<(total4 + 255) / 256, 256>>>(out, bias);

    dim3 grid(M_PAIRS / (WARPS_PER_BLOCK * PAIRS_PER_WARP), K_OFF);
    scatter_gemm_kernel<<<grid, WARPS_PER_BLOCK * 32>>>(
        input, kernelw, in_map, out_map, out);
}

// round 5
// speedup vs baseline: 2.8442x; 2.2528x over previous
#include <cuda_runtime.h>
#include <cstdint>

#define N_VOX   262144
#define M_PAIRS 131072
#define K_OFF   27
#define C       32

// ---------------------------------------------------------------------------
// Kernel 1: out[n][c] = bias[c]  (bias add commutes with the scatter-adds)
// ---------------------------------------------------------------------------
__global__ void bias_init_kernel(float* __restrict__ out,
                                 const float* __restrict__ bias)
{
    int t = blockIdx.x * blockDim.x + threadIdx.x;
    const int total4 = N_VOX * (C / 4);
    if (t < total4) {
        const float4* b4 = (const float4*)bias;
        float4* o4 = (float4*)out;
        o4[t] = b4[t & 7];
    }
}

// ---------------------------------------------------------------------------
// Kernel 2: staged gather -> smem -> f32x2 GEMM -> RED scatter.
//
//   Stage: 256 input rows gathered cooperatively & coalesced (8 lanes x
//          float4 per row) -> smem. 1 L1 wavefront per pair instead of the
//          32-wavefront broadcast replication of the lane=channel scheme.
//   Math:  per warp, 32 pairs; input row re-read via uniform LDS.128
//          (smem broadcast is free), weights register-resident as f32x2.
//   Scatter: scalar RED.E.ADD.F32 per lane.
// ---------------------------------------------------------------------------
#define THREADS          256
#define WARPS_PER_BLOCK  8
#define PAIRS_PER_BLOCK  256
#define PAIRS_PER_WARP   (PAIRS_PER_BLOCK / WARPS_PER_BLOCK)   // 32

__global__ __launch_bounds__(THREADS)
void scatter_gemm_kernel(const float* __restrict__ input,
                         const float* __restrict__ kernel,
                         const int*   __restrict__ in_map,
                         const int*   __restrict__ out_map,
                         float*       __restrict__ out)
{
    __shared__ float srow[PAIRS_PER_BLOCK][C];    // 32 KB staged rows

    const int k    = blockIdx.y;
    const int lane = threadIdx.x & 31;
    const int warp = threadIdx.x >> 5;

    const int tile = blockIdx.x * PAIRS_PER_BLOCK;
    const int* im  = in_map  + k * M_PAIRS + tile;
    const int* om  = out_map + k * M_PAIRS + tile;

    // ---- Stage: 256 rows x 8 quads = 2048 float4, 8 per thread, coalesced.
    #pragma unroll
    for (int i = 0; i < (PAIRS_PER_BLOCK * (C / 4)) / THREADS; i++) {
        int q  = threadIdx.x + i * THREADS;     // quad id
        int pr = q >> 3;                        // pair within tile
        int qq = q & 7;                         // quad within row
        int irow = __ldg(im + pr);              // 4 distinct addrs/warp: 1 sector
        ((float4*)srow)[q] = __ldg((const float4*)(input + (size_t)irow * C) + qq);
    }

    // ---- Weights: f32x2-packed column for this lane (overlaps with staging).
    const float* Wk = kernel + k * C * C;
    unsigned long long wp[C / 2];
    #pragma unroll
    for (int j = 0; j < C / 2; j++) {
        float w0 = __ldg(Wk + (2 * j)     * C + lane);
        float w1 = __ldg(Wk + (2 * j + 1) * C + lane);
        asm("mov.b64 %0, {%1, %2};" : "=l"(wp[j]) : "f"(w0), "f"(w1));
    }

    __syncthreads();

    // ---- Compute + scatter: warp w owns pairs [w*32, w*32+32).
    const int pbase = warp * PAIRS_PER_WARP;

    #pragma unroll 4
    for (int p = 0; p < PAIRS_PER_WARP; p++) {
        const int pr   = pbase + p;
        const int orow = __ldg(om + pr);        // uniform -> broadcast, L1 hit

        const float4* r4 = (const float4*)&srow[pr][0];

        unsigned long long acc = 0ULL;          // packed (0.f, 0.f)
        #pragma unroll
        for (int j = 0; j < C / 4; j++) {
            float4 a = r4[j];                   // uniform LDS.128: smem broadcast
            unsigned long long a01, a23;
            asm("mov.b64 %0, {%1, %2};" : "=l"(a01) : "f"(a.x), "f"(a.y));
            asm("mov.b64 %0, {%1, %2};" : "=l"(a23) : "f"(a.z), "f"(a.w));
            asm("fma.rn.f32x2 %0, %1, %2, %0;" : "+l"(acc) : "l"(a01), "l"(wp[2 * j]));
            asm("fma.rn.f32x2 %0, %1, %2, %0;" : "+l"(acc) : "l"(a23), "l"(wp[2 * j + 1]));
        }
        float lo, hi;
        asm("mov.b64 {%0, %1}, %2;" : "=f"(lo), "=f"(hi) : "l"(acc));

        atomicAdd(out + (size_t)orow * C + lane, lo + hi);   // RED.E.ADD.F32
    }
}

// ---------------------------------------------------------------------------
// Launch
// ---------------------------------------------------------------------------
extern "C" void kernel_launch(void* const* d_in, const int* in_sizes, int n_in,
                              void* d_out, int out_size)
{
    const float* input   = (const float*)d_in[0];
    const float* kernelw = (const float*)d_in[1];
    const float* bias    = (const float*)d_in[2];
    const int*   in_map  = (const int*)  d_in[3];
    const int*   out_map = (const int*)  d_in[4];
    float*       out     = (float*)d_out;

    const int total4 = N_VOX * (C / 4);
    bias_init_kernel<<<(total4 + 255) / 256, 256>>>(out, bias);

    dim3 grid(M_PAIRS / PAIRS_PER_BLOCK, K_OFF);
    scatter_gemm_kernel<<<grid, THREADS>>>(input, kernelw, in_map, out_map, out);
}

// round 6
// speedup vs baseline: 3.2808x; 1.1535x over previous
#include <cuda_runtime.h>
#include <cstdint>

#define N_VOX   262144
#define M_PAIRS 131072
#define K_OFF   27
#define C       32
#define CPAD    36        // row stride in floats: 16B pad -> halves hit disjoint banks

// ---------------------------------------------------------------------------
// Kernel 1: out[n][c] = bias[c]  (bias add commutes with the scatter-adds)
// ---------------------------------------------------------------------------
__global__ void bias_init_kernel(float* __restrict__ out,
                                 const float* __restrict__ bias)
{
    int t = blockIdx.x * blockDim.x + threadIdx.x;
    const int total4 = N_VOX * (C / 4);
    if (t < total4) {
        const float4* b4 = (const float4*)bias;
        float4* o4 = (float4*)out;
        o4[t] = b4[t & 7];
    }
}

// ---------------------------------------------------------------------------
// Kernel 2: staged gather -> smem -> f32x2 GEMM (2 pairs/warp) -> red.v2.
//
//   Stage:  256 rows gathered coalesced (8 lanes x float4 per row) into
//           padded smem rows (stride 36 floats).
//   Math:   each 16-lane half-warp owns one pair; lane covers 2 channels
//           (one f32x2 accumulator). Each LDS.128 feeds TWO pairs ->
//           4 LDS/pair instead of 8; padding makes the 2-address LDS
//           conflict-free.
//   Scatter: red.global.add.v2.f32 per lane (contiguous 128B per pair).
// ---------------------------------------------------------------------------
#define THREADS          256
#define WARPS_PER_BLOCK  8
#define PAIRS_PER_BLOCK  256
#define PAIRS_PER_WARP   (PAIRS_PER_BLOCK / WARPS_PER_BLOCK)   // 32
#define STEPS            (PAIRS_PER_WARP / 2)                  // 16 (2 pairs/step)

__global__ __launch_bounds__(THREADS)
void scatter_gemm_kernel(const float* __restrict__ input,
                         const float* __restrict__ kernel,
                         const int*   __restrict__ in_map,
                         const int*   __restrict__ out_map,
                         float*       __restrict__ out)
{
    __shared__ float srow[PAIRS_PER_BLOCK][CPAD];    // 36 KB staged rows

    const int k     = blockIdx.y;
    const int lane  = threadIdx.x & 31;
    const int warp  = threadIdx.x >> 5;
    const int half  = lane >> 4;          // which pair of the step
    const int chalf = lane & 15;          // channel pair: covers 2*chalf, 2*chalf+1

    const int tile = blockIdx.x * PAIRS_PER_BLOCK;
    const int* im  = in_map  + k * M_PAIRS + tile;
    const int* om  = out_map + k * M_PAIRS + tile;

    // ---- Stage: 256 rows x 8 quads, coalesced; 8 float4 per thread.
    #pragma unroll
    for (int i = 0; i < (PAIRS_PER_BLOCK * (C / 4)) / THREADS; i++) {
        int q  = threadIdx.x + i * THREADS;
        int pr = q >> 3;
        int qq = q & 7;
        int irow = __ldg(im + pr);
        ((float4*)&srow[pr][0])[qq] =
            __ldg((const float4*)(input + (size_t)irow * C) + qq);
    }

    // ---- Weights: lane's 2 output channels, packed f32x2 per input channel.
    const float* Wk = kernel + k * C * C;
    unsigned long long wp[C];
    #pragma unroll
    for (int i = 0; i < C; i++) {
        float2 w2 = __ldg((const float2*)(Wk + i * C) + chalf);
        asm("mov.b64 %0, {%1, %2};" : "=l"(wp[i]) : "f"(w2.x), "f"(w2.y));
    }

    __syncthreads();

    const int pbase = warp * PAIRS_PER_WARP;

    #pragma unroll 4
    for (int t = 0; t < STEPS; t++) {
        const int pr   = pbase + 2 * t + half;
        const int orow = __ldg(om + pr);        // 2 distinct addrs per warp

        const float4* r4 = (const float4*)&srow[pr][0];

        unsigned long long acc = 0ULL;          // packed (0.f, 0.f)
        #pragma unroll
        for (int j = 0; j < C / 4; j++) {
            float4 a = r4[j];                   // 2-addr LDS.128, conflict-free
            unsigned long long ax, ay, az, aw;
            asm("mov.b64 %0, {%1, %1};" : "=l"(ax) : "f"(a.x));
            asm("mov.b64 %0, {%1, %1};" : "=l"(ay) : "f"(a.y));
            asm("mov.b64 %0, {%1, %1};" : "=l"(az) : "f"(a.z));
            asm("mov.b64 %0, {%1, %1};" : "=l"(aw) : "f"(a.w));
            asm("fma.rn.f32x2 %0, %1, %2, %0;" : "+l"(acc) : "l"(ax), "l"(wp[4 * j + 0]));
            asm("fma.rn.f32x2 %0, %1, %2, %0;" : "+l"(acc) : "l"(ay), "l"(wp[4 * j + 1]));
            asm("fma.rn.f32x2 %0, %1, %2, %0;" : "+l"(acc) : "l"(az), "l"(wp[4 * j + 2]));
            asm("fma.rn.f32x2 %0, %1, %2, %0;" : "+l"(acc) : "l"(aw), "l"(wp[4 * j + 3]));
        }
        float lo, hi;
        asm("mov.b64 {%0, %1}, %2;" : "=f"(lo), "=f"(hi) : "l"(acc));

        float* dst = out + (size_t)orow * C + 2 * chalf;   // 8B aligned
        asm volatile("red.global.add.v2.f32 [%0], {%1, %2};"
                     :: "l"(dst), "f"(lo), "f"(hi) : "memory");
    }
}

// ---------------------------------------------------------------------------
// Launch
// ---------------------------------------------------------------------------
extern "C" void kernel_launch(void* const* d_in, const int* in_sizes, int n_in,
                              void* d_out, int out_size)
{
    const float* input   = (const float*)d_in[0];
    const float* kernelw = (const float*)d_in[1];
    const float* bias    = (const float*)d_in[2];
    const int*   in_map  = (const int*)  d_in[3];
    const int*   out_map = (const int*)  d_in[4];
    float*       out     = (float*)d_out;

    const int total4 = N_VOX * (C / 4);
    bias_init_kernel<<<(total4 + 255) / 256, 256>>>(out, bias);

    dim3 grid(M_PAIRS / PAIRS_PER_BLOCK, K_OFF);
    scatter_gemm_kernel<<<grid, THREADS>>>(input, kernelw, in_map, out_map, out);
}